// round 2
// baseline (speedup 1.0000x reference)
#include <cuda_runtime.h>
#include <cuda_bf16.h>
#include <cstdint>

#define N_NODES 100000
#define DIM 128
#define NUM_LABELS 1024

// ---------------- scratch (no allocations allowed; float4 => 16B aligned) ----
__device__ float4 g_agg [ (size_t)N_NODES * (DIM/4) ];
__device__ float4 g_abuf[ (size_t)N_NODES * (DIM/4) ];
__device__ float4 g_h1  [ (size_t)N_NODES * (DIM/4) ];
__device__ float4 g_pool[ (size_t)N_NODES * (DIM/4) ];
__device__ int    g_idx64;

// ---------------- index-width detection (int32 vs int64 edge indices) -------
// An int64 node index < N_NODES always has a zero high word. If the buffer is
// really int32, the "high word" of slot i is edge-index 2i+1, which is ~never
// zero for 64 consecutive slots.
__global__ void detect_kernel(const unsigned long long* __restrict__ src) {
    if (threadIdx.x == 0 && blockIdx.x == 0) {
        int is64 = 1;
        for (int i = 0; i < 64; i++) {
            if (src[i] >> 32) { is64 = 0; break; }
        }
        g_idx64 = is64;
    }
}

// ---------------- zero kernel ----------------
__global__ void zero_kernel(float4* __restrict__ p, int n4) {
    int i = blockIdx.x * blockDim.x + threadIdx.x;
    int stride = gridDim.x * blockDim.x;
    float4 z = make_float4(0.f, 0.f, 0.f, 0.f);
    for (; i < n4; i += stride) p[i] = z;
}

// ---------------- scatter-add: one warp per edge ----------------
// agg[dst] += h[src], 128 floats per edge = 32 lanes x float4
__global__ void scatter_kernel(const float4* __restrict__ h,
                               const void* __restrict__ srcv,
                               const void* __restrict__ dstv,
                               float* __restrict__ agg, int nE)
{
    int w = (blockIdx.x * blockDim.x + threadIdx.x) >> 5;
    int lane = threadIdx.x & 31;
    if (w >= nE) return;
    long long s, d;
    if (g_idx64) {
        s = ((const long long*)srcv)[w];
        d = ((const long long*)dstv)[w];
    } else {
        s = ((const int*)srcv)[w];
        d = ((const int*)dstv)[w];
    }
    float4 v = h[(size_t)s * 32 + lane];
    float* p = agg + (size_t)d * 128 + lane * 4;
    asm volatile("red.global.add.v4.f32 [%0], {%1,%2,%3,%4};"
                 :: "l"(p), "f"(v.x), "f"(v.y), "f"(v.z), "f"(v.w) : "memory");
}

// ---------------- fused GEMM ----------------
//   MODE_GIN      : A' = (1+eps)*A + AGG ;  out = relu(acc + b)
//   MODE_RES      : A' = A ;               out = A[m][n] + relu(acc + b)
//   MODE_RES_POOL : A' = A ;               out = 0.5*(H1[m][n] + A[m][n] + relu(acc+b))
//   MODE_FINAL    : A' = A ;               out = acc + b
#define MODE_GIN 0
#define MODE_RES 1
#define MODE_RES_POOL 2
#define MODE_FINAL 3

#define TM 128
#define TN 128
#define TK 32

template <int MODE>
__global__ __launch_bounds__(256)
void gemm_kernel(const float* __restrict__ A,
                 const float* __restrict__ AGG,
                 const float* __restrict__ H1,
                 const float* __restrict__ epsp,
                 const float* __restrict__ W,
                 const float* __restrict__ bias,
                 float* __restrict__ out,
                 int M, int Nout)
{
    __shared__ float As[TM][TK];
    __shared__ float Bs[TK][TN];

    const int tid = threadIdx.x;
    const int tx = tid & 15;    // 0..15 -> col group
    const int ty = tid >> 4;    // 0..15 -> row group
    const int row0 = blockIdx.y * TM;
    const int col0 = blockIdx.x * TN;

    float acc[8][8];
    #pragma unroll
    for (int i = 0; i < 8; i++)
        #pragma unroll
        for (int j = 0; j < 8; j++) acc[i][j] = 0.f;

    float eps1 = 0.f;
    if (MODE == MODE_GIN) eps1 = 1.0f + epsp[0];

    for (int k0 = 0; k0 < DIM; k0 += TK) {
        // A tile: 128 rows x 32 cols = 1024 float4, 4 per thread
        #pragma unroll
        for (int i = 0; i < 4; i++) {
            int idx = tid + i * 256;
            int m = idx >> 3;       // row in tile
            int kq = idx & 7;       // float4 col
            int gm = row0 + m;
            float4 v = make_float4(0.f, 0.f, 0.f, 0.f);
            if (gm < M) {
                v = *((const float4*)(A + (size_t)gm * DIM + k0) + kq);
                if (MODE == MODE_GIN) {
                    float4 g = *((const float4*)(AGG + (size_t)gm * DIM + k0) + kq);
                    v.x = eps1 * v.x + g.x;
                    v.y = eps1 * v.y + g.y;
                    v.z = eps1 * v.z + g.z;
                    v.w = eps1 * v.w + g.w;
                }
            }
            *((float4*)&As[m][kq * 4]) = v;
        }
        // B tile: 32 rows x 128 cols = 1024 float4, 4 per thread
        #pragma unroll
        for (int i = 0; i < 4; i++) {
            int idx = tid + i * 256;
            int kk = idx >> 5;      // 0..31
            int nq = idx & 31;      // float4 col
            float4 w = *((const float4*)(W + (size_t)(k0 + kk) * Nout + col0) + nq);
            *((float4*)&Bs[kk][nq * 4]) = w;
        }
        __syncthreads();

        #pragma unroll
        for (int k = 0; k < TK; k++) {
            float a[8], b[8];
            #pragma unroll
            for (int i = 0; i < 8; i++) a[i] = As[ty * 8 + i][k];
            *((float4*)&b[0]) = *((const float4*)&Bs[k][tx * 8]);
            *((float4*)&b[4]) = *((const float4*)&Bs[k][tx * 8 + 4]);
            #pragma unroll
            for (int i = 0; i < 8; i++)
                #pragma unroll
                for (int j = 0; j < 8; j++)
                    acc[i][j] += a[i] * b[j];
        }
        __syncthreads();
    }

    // epilogue
    #pragma unroll
    for (int i = 0; i < 8; i++) {
        int gm = row0 + ty * 8 + i;
        if (gm >= M) continue;
        #pragma unroll
        for (int jq = 0; jq < 2; jq++) {
            int gn = col0 + tx * 8 + jq * 4;
            float4 bb = *(const float4*)(bias + gn);
            float4 r;
            r.x = acc[i][jq * 4 + 0] + bb.x;
            r.y = acc[i][jq * 4 + 1] + bb.y;
            r.z = acc[i][jq * 4 + 2] + bb.z;
            r.w = acc[i][jq * 4 + 3] + bb.w;
            if (MODE == MODE_GIN || MODE == MODE_RES || MODE == MODE_RES_POOL) {
                r.x = fmaxf(r.x, 0.f);
                r.y = fmaxf(r.y, 0.f);
                r.z = fmaxf(r.z, 0.f);
                r.w = fmaxf(r.w, 0.f);
            }
            if (MODE == MODE_RES) {
                float4 a1 = *(const float4*)(A + (size_t)gm * DIM + gn);
                r.x += a1.x; r.y += a1.y; r.z += a1.z; r.w += a1.w;
            }
            if (MODE == MODE_RES_POOL) {
                float4 a2 = *(const float4*)(A + (size_t)gm * DIM + gn);
                float4 h1 = *(const float4*)(H1 + (size_t)gm * DIM + gn);
                r.x = 0.5f * (r.x + a2.x + h1.x);
                r.y = 0.5f * (r.y + a2.y + h1.y);
                r.z = 0.5f * (r.z + a2.z + h1.z);
                r.w = 0.5f * (r.w + a2.w + h1.w);
            }
            *(float4*)(out + (size_t)gm * Nout + gn) = r;
        }
    }
}

// ---------------- launch ----------------
extern "C" void kernel_launch(void* const* d_in, const int* in_sizes, int n_in,
                              void* d_out, int out_size)
{
    const float* X    = (const float*)d_in[0];
    const void*  src  = d_in[1];
    const void*  dst  = d_in[2];
    const float* eps1 = (const float*)d_in[3];
    const float* W1   = (const float*)d_in[4];
    const float* b1   = (const float*)d_in[5];
    const float* rW1  = (const float*)d_in[6];
    const float* rb1  = (const float*)d_in[7];
    const float* eps2 = (const float*)d_in[8];
    const float* W2   = (const float*)d_in[9];
    const float* b2   = (const float*)d_in[10];
    const float* rW2  = (const float*)d_in[11];
    const float* rb2  = (const float*)d_in[12];
    const float* linW = (const float*)d_in[13];
    const float* linb = (const float*)d_in[14];
    float* out = (float*)d_out;

    const int M  = in_sizes[0] / DIM;   // 100000
    const int nE = in_sizes[1];         // 1600000

    float4 *agg4, *abuf4, *h14, *pool4;
    cudaGetSymbolAddress((void**)&agg4,  g_agg);
    cudaGetSymbolAddress((void**)&abuf4, g_abuf);
    cudaGetSymbolAddress((void**)&h14,   g_h1);
    cudaGetSymbolAddress((void**)&pool4, g_pool);
    float* agg  = (float*)agg4;
    float* abuf = (float*)abuf4;
    float* h1   = (float*)h14;
    float* pool = (float*)pool4;

    const int n4 = M * (DIM / 4);
    const int zeroBlocks = 1024;
    const int scatterBlocks = (int)(((long long)nE * 32 + 255) / 256);

    dim3 g128(1, (M + TM - 1) / TM);                 // N = 128
    dim3 gfin(NUM_LABELS / TN, (M + TM - 1) / TM);   // N = 1024

    detect_kernel<<<1, 32>>>((const unsigned long long*)src);

    // ---- layer 1 ----
    zero_kernel<<<zeroBlocks, 256>>>(agg4, n4);
    scatter_kernel<<<scatterBlocks, 256>>>((const float4*)X, src, dst, agg, nE);
    gemm_kernel<MODE_GIN><<<g128, 256>>>(X, agg, nullptr, eps1, W1, b1, abuf, M, DIM);
    gemm_kernel<MODE_RES><<<g128, 256>>>(abuf, nullptr, nullptr, nullptr, rW1, rb1, h1, M, DIM);

    // ---- layer 2 ----
    zero_kernel<<<zeroBlocks, 256>>>(agg4, n4);
    scatter_kernel<<<scatterBlocks, 256>>>((const float4*)h1, src, dst, agg, nE);
    gemm_kernel<MODE_GIN><<<g128, 256>>>(h1, agg, nullptr, eps2, W2, b2, abuf, M, DIM);
    gemm_kernel<MODE_RES_POOL><<<g128, 256>>>(abuf, nullptr, h1, nullptr, rW2, rb2, pool, M, DIM);

    // ---- head ----
    gemm_kernel<MODE_FINAL><<<gfin, 256>>>(pool, nullptr, nullptr, nullptr, linW, linb, out, M, NUM_LABELS);
}